// round 5
// baseline (speedup 1.0000x reference)
#include <cuda_runtime.h>
#include <cstdint>

// Problem constants (fixed by the dataset)
constexpr int Bc = 8;
constexpr int Nc = 100000;
constexpr int Ec = 3200000;
constexpr int LOSS_BLOCKS = 128;

// Scratch (device globals — no allocation allowed in kernel_launch)
__device__ __align__(16) float g_heads_t[Nc * Bc];   // heads transposed to (N, 8)
__device__ __align__(16) float g_net[Nc * Bc];       // net_flows, node-major (N, 8)
__device__ float g_partials[LOSS_BLOCKS];            // continuity partial sums

__device__ __forceinline__ void red_add_v4(float* p, float4 v) {
    asm volatile("red.global.add.v4.f32 [%0], {%1, %2, %3, %4};"
                 :: "l"(__cvta_generic_to_global(p)),
                    "f"(v.x), "f"(v.y), "f"(v.z), "f"(v.w)
                 : "memory");
}

// ---------------------------------------------------------------------------
// Dummy kernel: aligns edge_kernel with ncu's profiled launch slot
// (profiled index ≡ 3 mod 6 given the harness's -s 5 -c 1 capture).
// ---------------------------------------------------------------------------
__global__ void dummy_kernel() {}

// ---------------------------------------------------------------------------
// Kernel 1: transpose heads (B,N)->(N,8), zero the net accumulator.
// One thread per (node, batch-half).
// ---------------------------------------------------------------------------
__global__ void prep_kernel(const float* __restrict__ heads) {
    int t = blockIdx.x * blockDim.x + threadIdx.x;
    int n = t >> 1;
    int h = t & 1;          // which half: batches 0-3 or 4-7
    if (n >= Nc) return;
    const float* hp = heads + (h * 4) * Nc + n;
    float4 a;
    a.x = hp[0 * Nc];
    a.y = hp[1 * Nc];
    a.z = hp[2 * Nc];
    a.w = hp[3 * Nc];
    reinterpret_cast<float4*>(g_heads_t)[2 * n + h] = a;
    reinterpret_cast<float4*>(g_net)[2 * n + h] = make_float4(0.f, 0.f, 0.f, 0.f);
}

// ---------------------------------------------------------------------------
// Kernel 2: per-edge — compute flows for all 8 batches, write flows (B,E),
// scatter-add into node-major net via vector REDs. (R2 form; flows stores
// marked evict-first to protect g_heads_t/g_net L2 residency.)
// edge_index is INT32 (JAX x64-disabled: "int64" randint is silently int32).
// ---------------------------------------------------------------------------
__global__ void __launch_bounds__(256)
edge_kernel(const int* __restrict__ ei,
            const float2* __restrict__ ea,
            float* __restrict__ flows) {
    int e = blockIdx.x * blockDim.x + threadIdx.x;   // grid is exact: Ec % 256 == 0

    int s = ei[e];
    int d = ei[Ec + e];
    float cond = ea[e].x;

    const float4* ht = reinterpret_cast<const float4*>(g_heads_t);
    float4 hs0 = ht[2 * s];
    float4 hs1 = ht[2 * s + 1];
    float4 hd0 = ht[2 * d];
    float4 hd1 = ht[2 * d + 1];

    float4 f0, f1;
    f0.x = cond * (hs0.x - hd0.x);
    f0.y = cond * (hs0.y - hd0.y);
    f0.z = cond * (hs0.z - hd0.z);
    f0.w = cond * (hs0.w - hd0.w);
    f1.x = cond * (hs1.x - hd1.x);
    f1.y = cond * (hs1.y - hd1.y);
    f1.z = cond * (hs1.z - hd1.z);
    f1.w = cond * (hs1.w - hd1.w);

    // flows output (B, E): coalesced across e; evict-first (write-once stream)
    __stcs(&flows[0 * (long long)Ec + e], f0.x);
    __stcs(&flows[1 * (long long)Ec + e], f0.y);
    __stcs(&flows[2 * (long long)Ec + e], f0.z);
    __stcs(&flows[3 * (long long)Ec + e], f0.w);
    __stcs(&flows[4 * (long long)Ec + e], f1.x);
    __stcs(&flows[5 * (long long)Ec + e], f1.y);
    __stcs(&flows[6 * (long long)Ec + e], f1.z);
    __stcs(&flows[7 * (long long)Ec + e], f1.w);

    if (s != d) {  // self-edge contributes exactly zero net flow
        red_add_v4(&g_net[s * 8],     f0);
        red_add_v4(&g_net[s * 8 + 4], f1);
        float4 n0 = make_float4(-f0.x, -f0.y, -f0.z, -f0.w);
        float4 n1 = make_float4(-f1.x, -f1.y, -f1.z, -f1.w);
        red_add_v4(&g_net[d * 8],     n0);
        red_add_v4(&g_net[d * 8 + 4], n1);
    }
}

// ---------------------------------------------------------------------------
// Deterministic block reduction helper (valid result on thread 0)
// ---------------------------------------------------------------------------
__device__ __forceinline__ float block_reduce(float v) {
    __shared__ float sh[32];
    int lane = threadIdx.x & 31;
    int wid  = threadIdx.x >> 5;
    #pragma unroll
    for (int o = 16; o; o >>= 1) v += __shfl_down_sync(0xffffffffu, v, o);
    if (lane == 0) sh[wid] = v;
    __syncthreads();
    int nw = blockDim.x >> 5;
    v = (threadIdx.x < nw) ? sh[threadIdx.x] : 0.f;
    if (wid == 0) {
        #pragma unroll
        for (int o = 16; o; o >>= 1) v += __shfl_down_sync(0xffffffffu, v, o);
    }
    return v;
}

// ---------------------------------------------------------------------------
// Kernel 3: continuity partial sums. Each thread handles one node (8 batches).
// ---------------------------------------------------------------------------
__global__ void loss_kernel(const float* __restrict__ demands) {
    float acc = 0.f;
    const float4* nf = reinterpret_cast<const float4*>(g_net);
    for (int n = blockIdx.x * blockDim.x + threadIdx.x; n < Nc;
         n += gridDim.x * blockDim.x) {
        float4 a = nf[2 * n];
        float4 b = nf[2 * n + 1];
        float v;
        v = a.x - demands[0 * Nc + n]; acc += v * v;
        v = a.y - demands[1 * Nc + n]; acc += v * v;
        v = a.z - demands[2 * Nc + n]; acc += v * v;
        v = a.w - demands[3 * Nc + n]; acc += v * v;
        v = b.x - demands[4 * Nc + n]; acc += v * v;
        v = b.y - demands[5 * Nc + n]; acc += v * v;
        v = b.z - demands[6 * Nc + n]; acc += v * v;
        v = b.w - demands[7 * Nc + n]; acc += v * v;
    }
    float s = block_reduce(acc);
    if (threadIdx.x == 0) g_partials[blockIdx.x] = s;
}

// ---------------------------------------------------------------------------
// Kernel 4: final — sum partials, boundary loss, write the 3 scalars.
// reservoir_nodes is INT32 (same JAX x64 trap).
// ---------------------------------------------------------------------------
__global__ void final_kernel(const float* __restrict__ heads,
                             const int* __restrict__ res,
                             const float* __restrict__ rhead,
                             float* __restrict__ out) {
    int tid = threadIdx.x;

    float acc = 0.f;
    for (int i = tid; i < LOSS_BLOCKS; i += blockDim.x) acc += g_partials[i];
    float csum = block_reduce(acc);
    __syncthreads();

    float rh = rhead[0];
    float acc2 = 0.f;
    for (int i = tid; i < Bc * 64; i += blockDim.x) {
        int b = i >> 6;
        int j = i & 63;
        int r = res[j];
        float v = heads[(long long)b * Nc + r] - rh;
        acc2 += v * v;
    }
    float bsum = block_reduce(acc2);

    if (tid == 0) {
        float c  = csum / (float)(Bc * Nc);
        float bl = bsum / (float)(Bc * 64);
        out[0] = c;
        out[1] = bl;
        out[2] = c + bl;  // LAMBDA_PHYSICS = 1.0
    }
}

// ---------------------------------------------------------------------------
// Launch: prep -> dummy -> dummy -> edge -> loss -> final (period 6 puts
// edge_kernel in ncu's profiled slot). Graph-capturable.
// ---------------------------------------------------------------------------
extern "C" void kernel_launch(void* const* d_in, const int* in_sizes, int n_in,
                              void* d_out, int out_size) {
    const float*  node_heads = (const float*)d_in[0];
    const float*  demands    = (const float*)d_in[1];
    const int*    edge_index = (const int*)d_in[2];     // int32!
    const float2* edge_attr  = (const float2*)d_in[3];
    const int*    res_nodes  = (const int*)d_in[4];     // int32!
    const float*  res_head   = (const float*)d_in[5];

    float* out   = (float*)d_out;
    float* flows = out + 3;  // output layout: [c, b, total, flows(8*E)]

    prep_kernel<<<(2 * Nc + 255) / 256, 256>>>(node_heads);
    dummy_kernel<<<1, 32>>>();
    dummy_kernel<<<1, 32>>>();
    edge_kernel<<<Ec / 256, 256>>>(edge_index, edge_attr, flows);
    loss_kernel<<<LOSS_BLOCKS, 256>>>(demands);
    final_kernel<<<1, 256>>>(node_heads, res_nodes, res_head, out);
}

// round 6
// speedup vs baseline: 1.0381x; 1.0381x over previous
#include <cuda_runtime.h>
#include <cstdint>

// Problem constants (fixed by the dataset)
constexpr int Bc = 8;
constexpr int Nc = 100000;
constexpr int Ec = 3200000;
constexpr int LOSS_BLOCKS = 196;   // 196*256*2 >= 2*Nc: exactly 2 nodes/thread

// Scratch (device globals — no allocation allowed in kernel_launch)
__device__ __align__(16) float g_heads_t[Nc * Bc];   // heads transposed to (N, 8)
__device__ __align__(16) float g_net[Nc * Bc];       // net_flows, node-major (N, 8)
__device__ float g_partials[LOSS_BLOCKS];            // continuity partial sums

__device__ __forceinline__ void red_add_v4(float* p, float4 v) {
    asm volatile("red.global.add.v4.f32 [%0], {%1, %2, %3, %4};"
                 :: "l"(__cvta_generic_to_global(p)),
                    "f"(v.x), "f"(v.y), "f"(v.z), "f"(v.w)
                 : "memory");
}

// ---------------------------------------------------------------------------
// Kernel 1: transpose heads (B,N)->(N,8), zero the net accumulator.
// One thread per (node, batch-half); 512-thread blocks (latency-bound kernel).
// ---------------------------------------------------------------------------
__global__ void __launch_bounds__(512)
prep_kernel(const float* __restrict__ heads) {
    int t = blockIdx.x * blockDim.x + threadIdx.x;
    int n = t >> 1;
    int h = t & 1;          // which half: batches 0-3 or 4-7
    if (n >= Nc) return;
    const float* hp = heads + (h * 4) * Nc + n;
    float4 a;
    a.x = hp[0 * Nc];
    a.y = hp[1 * Nc];
    a.z = hp[2 * Nc];
    a.w = hp[3 * Nc];
    reinterpret_cast<float4*>(g_heads_t)[2 * n + h] = a;
    reinterpret_cast<float4*>(g_net)[2 * n + h] = make_float4(0.f, 0.f, 0.f, 0.f);
}

// ---------------------------------------------------------------------------
// Kernel 2: per-edge — compute flows for all 8 batches, write flows (B,E),
// scatter-add into node-major net via vector REDs. (Measured-best R2 form:
// EPT=1, plain loads/stores. LTS-bound at ~81% — near the chip ceiling.)
// edge_index is INT32 (JAX x64-disabled: "int64" randint is silently int32).
// ---------------------------------------------------------------------------
__global__ void __launch_bounds__(256)
edge_kernel(const int* __restrict__ ei,
            const float2* __restrict__ ea,
            float* __restrict__ flows) {
    int e = blockIdx.x * blockDim.x + threadIdx.x;   // grid exact: Ec % 256 == 0

    int s = ei[e];
    int d = ei[Ec + e];
    float cond = ea[e].x;

    const float4* ht = reinterpret_cast<const float4*>(g_heads_t);
    float4 hs0 = ht[2 * s];
    float4 hs1 = ht[2 * s + 1];
    float4 hd0 = ht[2 * d];
    float4 hd1 = ht[2 * d + 1];

    float4 f0, f1;
    f0.x = cond * (hs0.x - hd0.x);
    f0.y = cond * (hs0.y - hd0.y);
    f0.z = cond * (hs0.z - hd0.z);
    f0.w = cond * (hs0.w - hd0.w);
    f1.x = cond * (hs1.x - hd1.x);
    f1.y = cond * (hs1.y - hd1.y);
    f1.z = cond * (hs1.z - hd1.z);
    f1.w = cond * (hs1.w - hd1.w);

    // flows output (B, E): coalesced across e within each batch row.
    // NOTE: flows = d_out + 3 is only 4B-aligned — scalar stores are mandatory.
    flows[0 * (long long)Ec + e] = f0.x;
    flows[1 * (long long)Ec + e] = f0.y;
    flows[2 * (long long)Ec + e] = f0.z;
    flows[3 * (long long)Ec + e] = f0.w;
    flows[4 * (long long)Ec + e] = f1.x;
    flows[5 * (long long)Ec + e] = f1.y;
    flows[6 * (long long)Ec + e] = f1.z;
    flows[7 * (long long)Ec + e] = f1.w;

    if (s != d) {  // self-edge contributes exactly zero net flow
        red_add_v4(&g_net[s * 8],     f0);
        red_add_v4(&g_net[s * 8 + 4], f1);
        float4 n0 = make_float4(-f0.x, -f0.y, -f0.z, -f0.w);
        float4 n1 = make_float4(-f1.x, -f1.y, -f1.z, -f1.w);
        red_add_v4(&g_net[d * 8],     n0);
        red_add_v4(&g_net[d * 8 + 4], n1);
    }
}

// ---------------------------------------------------------------------------
// Deterministic block reduction helper (valid result on thread 0)
// ---------------------------------------------------------------------------
__device__ __forceinline__ float block_reduce(float v) {
    __shared__ float sh[32];
    int lane = threadIdx.x & 31;
    int wid  = threadIdx.x >> 5;
    #pragma unroll
    for (int o = 16; o; o >>= 1) v += __shfl_down_sync(0xffffffffu, v, o);
    if (lane == 0) sh[wid] = v;
    __syncthreads();
    int nw = blockDim.x >> 5;
    v = (threadIdx.x < nw) ? sh[threadIdx.x] : 0.f;
    if (wid == 0) {
        #pragma unroll
        for (int o = 16; o; o >>= 1) v += __shfl_down_sync(0xffffffffu, v, o);
    }
    return v;
}

// ---------------------------------------------------------------------------
// Kernel 3: continuity partial sums. Balanced grid: 2 nodes per thread.
// ---------------------------------------------------------------------------
__global__ void __launch_bounds__(256)
loss_kernel(const float* __restrict__ demands) {
    float acc = 0.f;
    const float4* nf = reinterpret_cast<const float4*>(g_net);
    for (int n = blockIdx.x * blockDim.x + threadIdx.x; n < Nc;
         n += gridDim.x * blockDim.x) {
        float4 a = nf[2 * n];
        float4 b = nf[2 * n + 1];
        float v;
        v = a.x - demands[0 * Nc + n]; acc += v * v;
        v = a.y - demands[1 * Nc + n]; acc += v * v;
        v = a.z - demands[2 * Nc + n]; acc += v * v;
        v = a.w - demands[3 * Nc + n]; acc += v * v;
        v = b.x - demands[4 * Nc + n]; acc += v * v;
        v = b.y - demands[5 * Nc + n]; acc += v * v;
        v = b.z - demands[6 * Nc + n]; acc += v * v;
        v = b.w - demands[7 * Nc + n]; acc += v * v;
    }
    float s = block_reduce(acc);
    if (threadIdx.x == 0) g_partials[blockIdx.x] = s;
}

// ---------------------------------------------------------------------------
// Kernel 4: final — sum partials, boundary loss, write the 3 scalars.
// reservoir_nodes is INT32 (same JAX x64 trap).
// ---------------------------------------------------------------------------
__global__ void final_kernel(const float* __restrict__ heads,
                             const int* __restrict__ res,
                             const float* __restrict__ rhead,
                             float* __restrict__ out) {
    int tid = threadIdx.x;

    float acc = 0.f;
    for (int i = tid; i < LOSS_BLOCKS; i += blockDim.x) acc += g_partials[i];
    float csum = block_reduce(acc);
    __syncthreads();

    float rh = rhead[0];
    float acc2 = 0.f;
    for (int i = tid; i < Bc * 64; i += blockDim.x) {
        int b = i >> 6;
        int j = i & 63;
        int r = res[j];
        float v = heads[(long long)b * Nc + r] - rh;
        acc2 += v * v;
    }
    float bsum = block_reduce(acc2);

    if (tid == 0) {
        float c  = csum / (float)(Bc * Nc);
        float bl = bsum / (float)(Bc * 64);
        out[0] = c;
        out[1] = bl;
        out[2] = c + bl;  // LAMBDA_PHYSICS = 1.0
    }
}

// ---------------------------------------------------------------------------
// Launch: prep -> edge -> loss -> final. Graph-capturable, no filler kernels.
// ---------------------------------------------------------------------------
extern "C" void kernel_launch(void* const* d_in, const int* in_sizes, int n_in,
                              void* d_out, int out_size) {
    const float*  node_heads = (const float*)d_in[0];
    const float*  demands    = (const float*)d_in[1];
    const int*    edge_index = (const int*)d_in[2];     // int32!
    const float2* edge_attr  = (const float2*)d_in[3];
    const int*    res_nodes  = (const int*)d_in[4];     // int32!
    const float*  res_head   = (const float*)d_in[5];

    float* out   = (float*)d_out;
    float* flows = out + 3;  // output layout: [c, b, total, flows(8*E)]

    prep_kernel<<<(2 * Nc + 511) / 512, 512>>>(node_heads);
    edge_kernel<<<Ec / 256, 256>>>(edge_index, edge_attr, flows);
    loss_kernel<<<LOSS_BLOCKS, 256>>>(demands);
    final_kernel<<<1, 256>>>(node_heads, res_nodes, res_head, out);
}

// round 7
// speedup vs baseline: 1.1439x; 1.1019x over previous
#include <cuda_runtime.h>
#include <cstdint>

// Problem constants (fixed by the dataset)
constexpr int Bc = 8;
constexpr int Nc = 100000;
constexpr int Ec = 3200000;
constexpr int LOSS_BLOCKS = 196;   // 196*256*2 >= 2*Nc: exactly 2 nodes/thread

// Scratch (device globals — no allocation allowed in kernel_launch)
__device__ __align__(16) float g_heads_t[Nc * Bc];   // heads transposed to (N, 8)
__device__ __align__(16) float g_net[Nc * Bc];       // net_flows, node-major (N, 8)
__device__ float g_partials[LOSS_BLOCKS];            // continuity partial sums

__device__ __forceinline__ void red_add_v4(float* p, float4 v) {
    asm volatile("red.global.add.v4.f32 [%0], {%1, %2, %3, %4};"
                 :: "l"(__cvta_generic_to_global(p)),
                    "f"(v.x), "f"(v.y), "f"(v.z), "f"(v.w)
                 : "memory");
}

// ---------------------------------------------------------------------------
// Kernel 1: transpose heads (B,N)->(N,8), zero the net accumulator.
// One thread per (node, batch-half); 512-thread blocks (latency-bound kernel).
// ---------------------------------------------------------------------------
__global__ void __launch_bounds__(512)
prep_kernel(const float* __restrict__ heads) {
    int t = blockIdx.x * blockDim.x + threadIdx.x;
    int n = t >> 1;
    int h = t & 1;          // which half: batches 0-3 or 4-7
    if (n >= Nc) return;
    const float* hp = heads + (h * 4) * Nc + n;
    float4 a;
    a.x = hp[0 * Nc];
    a.y = hp[1 * Nc];
    a.z = hp[2 * Nc];
    a.w = hp[3 * Nc];
    reinterpret_cast<float4*>(g_heads_t)[2 * n + h] = a;
    reinterpret_cast<float4*>(g_net)[2 * n + h] = make_float4(0.f, 0.f, 0.f, 0.f);
}

// ---------------------------------------------------------------------------
// Kernel 2: lane-pair decomposition — 2 threads per edge (even lane: batches
// 0-3, odd lane: batches 4-7). Adjacent lanes touch the SAME 128-B L1 line
// per gathered endpoint -> gather L1 wavefronts halve vs one-thread-per-edge.
// ei/ea loads are pair-broadcast (merged); LTS sector traffic unchanged.
// edge_index is INT32 (JAX x64-disabled: "int64" randint is silently int32).
// ---------------------------------------------------------------------------
__global__ void __launch_bounds__(256)
edge_kernel(const int* __restrict__ ei,
            const float2* __restrict__ ea,
            float* __restrict__ flows) {
    int t = blockIdx.x * blockDim.x + threadIdx.x;   // grid exact: 2*Ec % 256 == 0
    int e = t >> 1;
    int h = t & 1;          // batch half

    int s = ei[e];
    int d = ei[Ec + e];
    float cond = ea[e].x;

    const float4* ht = reinterpret_cast<const float4*>(g_heads_t);
    float4 hs = ht[2 * s + h];
    float4 hd = ht[2 * d + h];

    float4 f;
    f.x = cond * (hs.x - hd.x);
    f.y = cond * (hs.y - hd.y);
    f.z = cond * (hs.z - hd.z);
    f.w = cond * (hs.w - hd.w);

    // flows output (B, E): per batch row, same-parity lanes write consecutive e.
    // NOTE: flows = d_out + 3 is only 4B-aligned — scalar stores are mandatory.
    long long b0 = (long long)(4 * h) * Ec + e;
    flows[b0]           = f.x;
    flows[b0 + 1LL*Ec]  = f.y;
    flows[b0 + 2LL*Ec]  = f.z;
    flows[b0 + 3LL*Ec]  = f.w;

    if (s != d) {  // self-edge contributes exactly zero net flow
        red_add_v4(&g_net[s * 8 + 4 * h], f);
        float4 nf = make_float4(-f.x, -f.y, -f.z, -f.w);
        red_add_v4(&g_net[d * 8 + 4 * h], nf);
    }
}

// ---------------------------------------------------------------------------
// Deterministic block reduction helper (valid result on thread 0)
// ---------------------------------------------------------------------------
__device__ __forceinline__ float block_reduce(float v) {
    __shared__ float sh[32];
    int lane = threadIdx.x & 31;
    int wid  = threadIdx.x >> 5;
    #pragma unroll
    for (int o = 16; o; o >>= 1) v += __shfl_down_sync(0xffffffffu, v, o);
    if (lane == 0) sh[wid] = v;
    __syncthreads();
    int nw = blockDim.x >> 5;
    v = (threadIdx.x < nw) ? sh[threadIdx.x] : 0.f;
    if (wid == 0) {
        #pragma unroll
        for (int o = 16; o; o >>= 1) v += __shfl_down_sync(0xffffffffu, v, o);
    }
    return v;
}

// ---------------------------------------------------------------------------
// Kernel 3: continuity partial sums. Balanced grid: 2 nodes per thread.
// ---------------------------------------------------------------------------
__global__ void __launch_bounds__(256)
loss_kernel(const float* __restrict__ demands) {
    float acc = 0.f;
    const float4* nf = reinterpret_cast<const float4*>(g_net);
    for (int n = blockIdx.x * blockDim.x + threadIdx.x; n < Nc;
         n += gridDim.x * blockDim.x) {
        float4 a = nf[2 * n];
        float4 b = nf[2 * n + 1];
        float v;
        v = a.x - demands[0 * Nc + n]; acc += v * v;
        v = a.y - demands[1 * Nc + n]; acc += v * v;
        v = a.z - demands[2 * Nc + n]; acc += v * v;
        v = a.w - demands[3 * Nc + n]; acc += v * v;
        v = b.x - demands[4 * Nc + n]; acc += v * v;
        v = b.y - demands[5 * Nc + n]; acc += v * v;
        v = b.z - demands[6 * Nc + n]; acc += v * v;
        v = b.w - demands[7 * Nc + n]; acc += v * v;
    }
    float s = block_reduce(acc);
    if (threadIdx.x == 0) g_partials[blockIdx.x] = s;
}

// ---------------------------------------------------------------------------
// Kernel 4: final — sum partials, boundary loss, write the 3 scalars.
// reservoir_nodes is INT32 (same JAX x64 trap).
// ---------------------------------------------------------------------------
__global__ void final_kernel(const float* __restrict__ heads,
                             const int* __restrict__ res,
                             const float* __restrict__ rhead,
                             float* __restrict__ out) {
    int tid = threadIdx.x;

    float acc = 0.f;
    for (int i = tid; i < LOSS_BLOCKS; i += blockDim.x) acc += g_partials[i];
    float csum = block_reduce(acc);
    __syncthreads();

    float rh = rhead[0];
    float acc2 = 0.f;
    for (int i = tid; i < Bc * 64; i += blockDim.x) {
        int b = i >> 6;
        int j = i & 63;
        int r = res[j];
        float v = heads[(long long)b * Nc + r] - rh;
        acc2 += v * v;
    }
    float bsum = block_reduce(acc2);

    if (tid == 0) {
        float c  = csum / (float)(Bc * Nc);
        float bl = bsum / (float)(Bc * 64);
        out[0] = c;
        out[1] = bl;
        out[2] = c + bl;  // LAMBDA_PHYSICS = 1.0
    }
}

// ---------------------------------------------------------------------------
// Launch: prep -> edge -> loss -> final. Graph-capturable.
// ---------------------------------------------------------------------------
extern "C" void kernel_launch(void* const* d_in, const int* in_sizes, int n_in,
                              void* d_out, int out_size) {
    const float*  node_heads = (const float*)d_in[0];
    const float*  demands    = (const float*)d_in[1];
    const int*    edge_index = (const int*)d_in[2];     // int32!
    const float2* edge_attr  = (const float2*)d_in[3];
    const int*    res_nodes  = (const int*)d_in[4];     // int32!
    const float*  res_head   = (const float*)d_in[5];

    float* out   = (float*)d_out;
    float* flows = out + 3;  // output layout: [c, b, total, flows(8*E)]

    prep_kernel<<<(2 * Nc + 511) / 512, 512>>>(node_heads);
    edge_kernel<<<(2 * Ec) / 256, 256>>>(edge_index, edge_attr, flows);
    loss_kernel<<<LOSS_BLOCKS, 256>>>(demands);
    final_kernel<<<1, 256>>>(node_heads, res_nodes, res_head, out);
}